// round 3
// baseline (speedup 1.0000x reference)
#include <cuda_runtime.h>
#include <cstdint>
#include <math.h>

// SpatialGRU: B=256, C=128, L1=L2=32, U=128 — single persistent kernel,
// tf32 mma.sync m16n8k8, 128x128x32 tiles, cp.async double-buffered,
// per-diagonal software grid barrier, GEMM2 fused via completion counters.

#define NP  1024
#define BSZ 256

// ---- device scratch (no allocation allowed) ----
__device__ float g_T [NP * BSZ * 128];   // s, tf32-rounded
__device__ float g_H [NP * BSZ * 128];   // h, full fp32 (epilogue)
__device__ float g_Hr[NP * BSZ * 128];   // h, tf32-rounded (MMA)
__device__ float g_Wp[512 * 896];        // col-permuted W, tf32-rounded
__device__ float g_U2[512 * 128];        // [Umat; w_ij], tf32-rounded
__device__ float g_bP[896];              // permuted bias
__device__ float g_A2[8192 * 384];       // GEMM2 A, tf32-rounded
__device__ float g_Z [8192 * 512];       // softmaxed gates [m][u*4+g]
__device__ unsigned g_sync[64 + 63 * 64]; // [0:64) barrier counts, [64:) cell counters

__device__ __forceinline__ float to_tf32(float x) {
    float r; asm("cvt.rna.tf32.f32 %0, %1;" : "=f"(r) : "f"(x)); return r;
}
__device__ __forceinline__ void mma8(float* c, const uint32_t* a, const uint32_t* b) {
    asm volatile("mma.sync.aligned.m16n8k8.row.col.f32.tf32.tf32.f32 "
        "{%0,%1,%2,%3},{%4,%5,%6,%7},{%8,%9},{%0,%1,%2,%3};"
        : "+f"(c[0]), "+f"(c[1]), "+f"(c[2]), "+f"(c[3])
        : "r"(a[0]), "r"(a[1]), "r"(a[2]), "r"(a[3]), "r"(b[0]), "r"(b[1]));
}
__device__ __forceinline__ void cp16(uint32_t dst, const void* src, int sz) {
    asm volatile("cp.async.cg.shared.global [%0], [%1], 16, %2;" :: "r"(dst), "l"(src), "r"(sz));
}

// ---------------------------------------------------------------------------
// setup kernels
__global__ void init_sync_kernel() {
    int idx = blockIdx.x * 256 + threadIdx.x;
    if (idx < 64 + 63 * 64) g_sync[idx] = 0u;
}
__global__ void transpose_kernel(const float* __restrict__ in) {
    __shared__ float tile[32][33];
    int x  = blockIdx.x * 32 + threadIdx.x;
    int y0 = blockIdx.y * 32;
#pragma unroll
    for (int r = 0; r < 4; r++) {
        int y = y0 + threadIdx.y + r * 8;
        tile[threadIdx.y + r * 8][threadIdx.x] = in[(size_t)y * 1024 + x];
    }
    __syncthreads();
    int xo  = blockIdx.y * 32 + threadIdx.x;
    int yo0 = blockIdx.x * 32;
#pragma unroll
    for (int r = 0; r < 4; r++) {
        int yo = yo0 + threadIdx.y + r * 8;
        g_T[(size_t)yo * 32768 + xo] = to_tf32(tile[threadIdx.x][threadIdx.y + r * 8]);
    }
}
__global__ void prep_w_kernel(const float* __restrict__ W) {
    int idx = blockIdx.x * 256 + threadIdx.x;
    if (idx >= 512 * 896) return;
    int k = idx / 896, c = idx - k * 896;
    float v;
    if (c < 384) v = W[(size_t)k * 896 + c];
    else {
        int cc = c - 384, u = cc >> 2, g = cc & 3;
        v = W[(size_t)k * 896 + 384 + g * 128 + u];
    }
    g_Wp[idx] = to_tf32(v);
}
__global__ void prep_u2_kernel(const float* __restrict__ Umat, const float* __restrict__ w_ij) {
    int idx = blockIdx.x * 256 + threadIdx.x;
    if (idx >= 512 * 128) return;
    int k = idx >> 7;
    g_U2[idx] = to_tf32((k < 384) ? Umat[idx] : w_ij[idx - 384 * 128]);
}
__global__ void prep_b_kernel(const float* __restrict__ bias) {
    int c = blockIdx.x * 256 + threadIdx.x;
    if (c >= 896) return;
    if (c < 384) g_bP[c] = bias[c];
    else {
        int cc = c - 384, u = cc >> 2, g = cc & 3;
        g_bP[c] = bias[384 + g * 128 + u];
    }
}

// ---------------------------------------------------------------------------
#define ASTR 36
#define BSTR 132
#define ASZ  (128 * ASTR)
#define BSZT (32 * BSTR)
#define SMEM_BYTES ((2 * ASZ + 2 * BSZT) * 4)   // 70656

// GEMM1 for one (Mtile, Ntile): rz = q @ Wp, gate epilogue -> g_A2 / g_Z
__device__ void do_gemm1(int d, int i0, int Mbase, int nc0, float* sm) {
    float* Abuf[2] = { sm, sm + ASZ };
    float* Bbuf[2] = { sm + 2 * ASZ, sm + 2 * ASZ + BSZT };
    const int tid = threadIdx.x, lane = tid & 31, warp = tid >> 5;
    const int wm = warp >> 1, wn = warp & 1, qj = lane & 3, ql = lane >> 2;
    const int cell = Mbase >> 8, b0 = Mbase & 255;
    const int i = i0 + cell, j = d - i, p = i * 32 + j;

    const float* src[4]; int vld[4];
    vld[0] = (i > 0) ? 16 : 0;
    vld[1] = (j > 0) ? 16 : 0;
    vld[2] = (i > 0 && j > 0) ? 16 : 0;
    vld[3] = 16;
    src[0] = vld[0] ? g_Hr + ((size_t)(p - 32) * BSZ + b0) * 128 : g_T;
    src[1] = vld[1] ? g_Hr + ((size_t)(p - 1 ) * BSZ + b0) * 128 : g_T;
    src[2] = vld[2] ? g_Hr + ((size_t)(p - 33) * BSZ + b0) * 128 : g_T;
    src[3] = g_T + ((size_t)p * BSZ + b0) * 128;

    float acc[2][8][4] = {};

#define STAGE1(t, buf) do {                                                     \
        int seg_ = (t) >> 2;                                                    \
        const float* sp_ = src[seg_]; int v_ = vld[seg_];                       \
        int koff4_ = ((t) & 3) * 8;                                             \
        uint32_t aB_ = (uint32_t)__cvta_generic_to_shared(Abuf[buf]);           \
        uint32_t bB_ = (uint32_t)__cvta_generic_to_shared(Bbuf[buf]);           \
        _Pragma("unroll")                                                       \
        for (int r_ = 0; r_ < 4; r_++) {                                        \
            int idx_ = tid + r_ * 256;                                          \
            int m_ = idx_ >> 3, k4_ = idx_ & 7;                                 \
            cp16(aB_ + (m_ * ASTR + k4_ * 4) * 4,                               \
                 sp_ + (size_t)m_ * 128 + (koff4_ + k4_) * 4, v_);              \
        }                                                                       \
        const float* wp_ = g_Wp + (size_t)(t) * 32 * 896 + nc0;                 \
        _Pragma("unroll")                                                       \
        for (int r_ = 0; r_ < 4; r_++) {                                        \
            int idx_ = tid + r_ * 256;                                          \
            int k_ = idx_ >> 5, n4_ = idx_ & 31;                                \
            cp16(bB_ + (k_ * BSTR + n4_ * 4) * 4,                               \
                 wp_ + (size_t)k_ * 896 + n4_ * 4, 16);                         \
        }                                                                       \
        asm volatile("cp.async.commit_group;");                                 \
    } while (0)

    STAGE1(0, 0);
#pragma unroll 1
    for (int t = 0; t < 16; t++) {
        int buf = t & 1;
        if (t < 15) { STAGE1(t + 1, buf ^ 1); asm volatile("cp.async.wait_group 1;"); }
        else        { asm volatile("cp.async.wait_group 0;"); }
        __syncthreads();
        const uint32_t* A = (const uint32_t*)Abuf[buf];
        const uint32_t* B = (const uint32_t*)Bbuf[buf];
#pragma unroll
        for (int k8 = 0; k8 < 4; k8++) {
            int kb = k8 * 8;
            uint32_t af[2][4];
#pragma unroll
            for (int mt = 0; mt < 2; mt++) {
                int r = wm * 32 + mt * 16 + ql;
                int k = kb + qj;
                af[mt][0] = A[r * ASTR + k];       af[mt][1] = A[(r + 8) * ASTR + k];
                af[mt][2] = A[r * ASTR + k + 4];   af[mt][3] = A[(r + 8) * ASTR + k + 4];
            }
#pragma unroll
            for (int nt = 0; nt < 8; nt++) {
                int n = wn * 64 + nt * 8 + ql;
                int k = kb + qj;
                uint32_t bf[2] = { B[k * BSTR + n], B[(k + 4) * BSTR + n] };
                mma8(acc[0][nt], af[0], bf);
                mma8(acc[1][nt], af[1], bf);
            }
        }
        __syncthreads();
    }

    if (nc0 < 384) {
        const float* hsrc[3];
        hsrc[0] = (j > 0)          ? g_H + ((size_t)(p - 1 ) * BSZ + b0) * 128 : nullptr;
        hsrc[1] = (i > 0)          ? g_H + ((size_t)(p - 32) * BSZ + b0) * 128 : nullptr;
        hsrc[2] = (i > 0 && j > 0) ? g_H + ((size_t)(p - 33) * BSZ + b0) * 128 : nullptr;
#pragma unroll
        for (int mt = 0; mt < 2; mt++) {
#pragma unroll
            for (int half = 0; half < 2; half++) {
                int lr = wm * 32 + mt * 16 + ql + half * 8;
                int Mr = Mbase + lr;
#pragma unroll
                for (int nt = 0; nt < 8; nt++) {
                    int c = nc0 + wn * 64 + nt * 8 + 2 * qj;
                    float v0 = acc[mt][nt][half * 2 + 0] + g_bP[c];
                    float v1 = acc[mt][nt][half * 2 + 1] + g_bP[c + 1];
                    v0 = fminf(fmaxf(0.2f * v0 + 0.5f, 0.f), 1.f);
                    v1 = fminf(fmaxf(0.2f * v1 + 0.5f, 0.f), 1.f);
                    int seg = c >> 7, u = c & 127;
                    const float* hp = hsrc[seg];
                    float h0 = hp ? hp[lr * 128 + u]     : 0.f;
                    float h1 = hp ? hp[lr * 128 + u + 1] : 0.f;
                    *(float2*)&g_A2[(size_t)Mr * 384 + c] =
                        make_float2(to_tf32(v0 * h0), to_tf32(v1 * h1));
                }
            }
        }
    } else {
#pragma unroll
        for (int mt = 0; mt < 2; mt++) {
#pragma unroll
            for (int half = 0; half < 2; half++) {
                int lr = wm * 32 + mt * 16 + ql + half * 8;
                int Mr = Mbase + lr;
#pragma unroll
                for (int nt = 0; nt < 8; nt++) {
                    int c = nc0 + wn * 64 + nt * 8 + 2 * qj;
                    float z0 = acc[mt][nt][half * 2 + 0] + g_bP[c];
                    float z1 = acc[mt][nt][half * 2 + 1] + g_bP[c + 1];
                    float q0 = __shfl_xor_sync(0xffffffffu, z0, 1);
                    float q1 = __shfl_xor_sync(0xffffffffu, z1, 1);
                    float mx = fmaxf(fmaxf(z0, z1), fmaxf(q0, q1));
                    float e0 = __expf(z0 - mx), e1 = __expf(z1 - mx);
                    float s2 = e0 + e1;
                    float st = s2 + __shfl_xor_sync(0xffffffffu, s2, 1);
                    float inv = 1.f / st;
                    int cc = c - 384, u = cc >> 2, g = cc & 3;
                    *(float2*)&g_Z[(size_t)Mr * 512 + u * 4 + g] =
                        make_float2(e0 * inv, e1 * inv);
                }
            }
        }
    }
}

// GEMM2 for one Mtile: hstar = tanh(A2 @ U2 + b_ij); blend with gates -> g_H/g_Hr
__device__ void do_gemm2(int d, int i0, int Mbase, float* sm,
                         const float* __restrict__ bias, float* __restrict__ out) {
    float* Abuf[2] = { sm, sm + ASZ };
    float* Bbuf[2] = { sm + 2 * ASZ, sm + 2 * ASZ + BSZT };
    const int tid = threadIdx.x, lane = tid & 31, warp = tid >> 5;
    const int wm = warp >> 1, wn = warp & 1, qj = lane & 3, ql = lane >> 2;
    const int cell = Mbase >> 8, b0 = Mbase & 255;
    const int i = i0 + cell, j = d - i, p = i * 32 + j;

    const float* Tsrc = g_T + ((size_t)p * BSZ + b0) * 128;
    float acc[2][8][4] = {};

#define STAGE2(t, buf) do {                                                     \
        uint32_t aB_ = (uint32_t)__cvta_generic_to_shared(Abuf[buf]);           \
        uint32_t bB_ = (uint32_t)__cvta_generic_to_shared(Bbuf[buf]);           \
        int tk_ = (t) * 32;                                                     \
        _Pragma("unroll")                                                       \
        for (int r_ = 0; r_ < 4; r_++) {                                        \
            int idx_ = tid + r_ * 256;                                          \
            int m_ = idx_ >> 3, k4_ = idx_ & 7;                                 \
            const float* sp_;                                                   \
            if ((t) < 12) sp_ = g_A2 + (size_t)(Mbase + m_) * 384 + tk_ + k4_ * 4; \
            else          sp_ = Tsrc + (size_t)m_ * 128 + (tk_ - 384) + k4_ * 4;   \
            cp16(aB_ + (m_ * ASTR + k4_ * 4) * 4, sp_, 16);                     \
        }                                                                       \
        _Pragma("unroll")                                                       \
        for (int r_ = 0; r_ < 4; r_++) {                                        \
            int idx_ = tid + r_ * 256;                                          \
            int k_ = idx_ >> 5, n4_ = idx_ & 31;                                \
            cp16(bB_ + (k_ * BSTR + n4_ * 4) * 4,                               \
                 g_U2 + (size_t)(tk_ + k_) * 128 + n4_ * 4, 16);                \
        }                                                                       \
        asm volatile("cp.async.commit_group;");                                 \
    } while (0)

    STAGE2(0, 0);
#pragma unroll 1
    for (int t = 0; t < 16; t++) {
        int buf = t & 1;
        if (t < 15) { STAGE2(t + 1, buf ^ 1); asm volatile("cp.async.wait_group 1;"); }
        else        { asm volatile("cp.async.wait_group 0;"); }
        __syncthreads();
        const uint32_t* A = (const uint32_t*)Abuf[buf];
        const uint32_t* B = (const uint32_t*)Bbuf[buf];
#pragma unroll
        for (int k8 = 0; k8 < 4; k8++) {
            int kb = k8 * 8;
            uint32_t af[2][4];
#pragma unroll
            for (int mt = 0; mt < 2; mt++) {
                int r = wm * 32 + mt * 16 + ql;
                int k = kb + qj;
                af[mt][0] = A[r * ASTR + k];       af[mt][1] = A[(r + 8) * ASTR + k];
                af[mt][2] = A[r * ASTR + k + 4];   af[mt][3] = A[(r + 8) * ASTR + k + 4];
            }
#pragma unroll
            for (int nt = 0; nt < 8; nt++) {
                int n = wn * 64 + nt * 8 + ql;
                int k = kb + qj;
                uint32_t bf[2] = { B[k * BSTR + n], B[(k + 4) * BSTR + n] };
                mma8(acc[0][nt], af[0], bf);
                mma8(acc[1][nt], af[1], bf);
            }
        }
        __syncthreads();
    }

    const float* hL = (j > 0)          ? g_H + ((size_t)(p - 1 ) * BSZ + b0) * 128 : nullptr;
    const float* hT = (i > 0)          ? g_H + ((size_t)(p - 32) * BSZ + b0) * 128 : nullptr;
    const float* hD = (i > 0 && j > 0) ? g_H + ((size_t)(p - 33) * BSZ + b0) * 128 : nullptr;
    float* Hd  = g_H  + ((size_t)p * BSZ + b0) * 128;
    float* Hrd = g_Hr + ((size_t)p * BSZ + b0) * 128;

#pragma unroll
    for (int mt = 0; mt < 2; mt++) {
#pragma unroll
        for (int half = 0; half < 2; half++) {
            int lr = wm * 32 + mt * 16 + ql + half * 8;
            int Mr = Mbase + lr;
#pragma unroll
            for (int nt = 0; nt < 8; nt++) {
                int u = wn * 64 + nt * 8 + 2 * qj;
                float a0 = acc[mt][nt][half * 2 + 0] + bias[896 + u];
                float a1 = acc[mt][nt][half * 2 + 1] + bias[896 + u + 1];
                float hs0 = tanhf(a0), hs1 = tanhf(a1);
                float4 z0 = *(const float4*)&g_Z[(size_t)Mr * 512 + u * 4];
                float4 z1 = *(const float4*)&g_Z[(size_t)Mr * 512 + (u + 1) * 4];
                float l0 = hL ? hL[lr * 128 + u] : 0.f, l1 = hL ? hL[lr * 128 + u + 1] : 0.f;
                float t0 = hT ? hT[lr * 128 + u] : 0.f, t1 = hT ? hT[lr * 128 + u + 1] : 0.f;
                float d0 = hD ? hD[lr * 128 + u] : 0.f, d1 = hD ? hD[lr * 128 + u + 1] : 0.f;
                float h0 = z0.y * l0 + z0.z * t0 + z0.w * d0 + z0.x * hs0;
                float h1 = z1.y * l1 + z1.z * t1 + z1.w * d1 + z1.x * hs1;
                *(float2*)&Hd [lr * 128 + u] = make_float2(h0, h1);
                *(float2*)&Hrd[lr * 128 + u] = make_float2(to_tf32(h0), to_tf32(h1));
                if (p == 1023)
                    *(float2*)&out[(size_t)(b0 + lr) * 128 + u] = make_float2(h0, h1);
            }
        }
    }
}

// ---------------------------------------------------------------------------
// persistent driver: one barrier per diagonal; GEMM2 run by 7th-finishing block
__global__ __launch_bounds__(256, 2) void gru_persist_kernel(
        int nblocks, const float* __restrict__ bias, float* __restrict__ out) {
    extern __shared__ float sm[];
    __shared__ int s_last;

    for (int d = 0; d <= 62; d++) {
        const int i0 = (d > 31) ? d - 31 : 0;
        const int i1 = (d < 31) ? d : 31;
        const int nc = i1 - i0 + 1;
        const int nA = 14 * nc;   // 7 ntiles x 2nc mtiles

        for (int it = blockIdx.x; it < nA; it += nblocks) {
            const int mt = it / 7, nt = it - mt * 7;
            do_gemm1(d, i0, mt * 128, nt * 128, sm);
            __threadfence();
            __syncthreads();
            if (threadIdx.x == 0) {
                unsigned old = atomicAdd(&g_sync[64 + d * 64 + mt], 1u);
                s_last = (old == 6u);
            }
            __syncthreads();
            if (s_last) {
                do_gemm2(d, i0, mt * 128, sm, bias, out);
                __threadfence();
            }
            __syncthreads();
        }

        // grid barrier for diagonal d (dedicated counter; no reset needed)
        __threadfence();
        __syncthreads();
        if (threadIdx.x == 0) {
            atomicAdd(&g_sync[d], 1u);
            while (atomicAdd(&g_sync[d], 0u) < (unsigned)nblocks) __nanosleep(64);
        }
        __syncthreads();
        __threadfence();
    }
}

// ---------------------------------------------------------------------------
extern "C" void kernel_launch(void* const* d_in, const int* in_sizes, int n_in,
                              void* d_out, int out_size) {
    const float* inputs = (const float*)d_in[0];
    const float* W      = (const float*)d_in[1];
    const float* Umat   = (const float*)d_in[2];
    const float* bias   = (const float*)d_in[3];
    const float* w_ij   = (const float*)d_in[4];
    float* out = (float*)d_out;

    cudaFuncSetAttribute(gru_persist_kernel,
                         cudaFuncAttributeMaxDynamicSharedMemorySize, SMEM_BYTES);

    int dev = 0, sms = 0, occ = 0;
    cudaGetDevice(&dev);
    cudaDeviceGetAttribute(&sms, cudaDevAttrMultiProcessorCount, dev);
    cudaOccupancyMaxActiveBlocksPerMultiprocessor(&occ, gru_persist_kernel, 256, SMEM_BYTES);
    if (occ > 2) occ = 2;
    if (occ < 1) occ = 1;
    int nblocks = sms * occ;

    init_sync_kernel<<<(64 + 63 * 64 + 255) / 256, 256>>>();
    transpose_kernel<<<dim3(32, 1024), dim3(32, 8)>>>(inputs);
    prep_w_kernel<<<(512 * 896 + 255) / 256, 256>>>(W);
    prep_u2_kernel<<<(512 * 128 + 255) / 256, 256>>>(Umat, w_ij);
    prep_b_kernel<<<4, 256>>>(bias);

    gru_persist_kernel<<<nblocks, 256, SMEM_BYTES>>>(nblocks, bias, out);

    (void)in_sizes; (void)n_in; (void)out_size;
}